// round 1
// baseline (speedup 1.0000x reference)
#include <cuda_runtime.h>
#include <cstdint>

// Problem constants
#define B_    8
#define S_    1024
#define DIN_  1280
#define RANK_ 64
#define DOUT_ 1280
#define DOWN_SIZE_ 81920   // RANK*DIN
#define EMB_STRIDE_ 163840 // DOWN_SIZE + UP_SIZE

// Intermediate h[B, S, RANK] — device global scratch (no allocations allowed)
__device__ float g_h[B_ * S_ * RANK_];

// ---------------- f32x2 helpers (Blackwell packed fp32) ----------------
__device__ __forceinline__ unsigned long long pack2(float lo, float hi) {
    unsigned long long r;
    asm("mov.b64 %0, {%1, %2};" : "=l"(r) : "f"(lo), "f"(hi));
    return r;
}
__device__ __forceinline__ unsigned long long fma2(unsigned long long a,
                                                   unsigned long long b,
                                                   unsigned long long c) {
    unsigned long long d;
    asm("fma.rn.f32x2 %0, %1, %2, %3;" : "=l"(d) : "l"(a), "l"(b), "l"(c));
    return d;
}
__device__ __forceinline__ void unpack2(unsigned long long v, float& lo, float& hi) {
    asm("mov.b64 {%0, %1}, %2;" : "=f"(lo), "=f"(hi) : "l"(v));
}

// =====================================================================
// Stage 1: h[b,s,r] = sum_d x[b,s,d] * w_down[b,r,d]
// Per-batch GEMM M=1024 (s), N=64 (r), K=1280 (d).
// CTA tile: 64(M) x 64(N), KT=32. Grid: (S/64, B) = (16, 8) = 128 CTAs.
// smem stored K-transposed: Xs[kk][m], Ws[kk][n] -> conflict-free LDS.128.
// Software-pipelined: LDG for next K-tile issued before compute of current.
// =====================================================================
#define KT 32

__global__ __launch_bounds__(256, 1)
void stage1_kernel(const float* __restrict__ x, const float* __restrict__ embed) {
    __shared__ float Xs[KT][64];
    __shared__ float Ws[KT][64];

    const int tid = threadIdx.x;
    const int b   = blockIdx.y;
    const int s0  = blockIdx.x * 64;

    // compute mapping: 4 rows x 4 cols per thread
    const int r0 = (tid >> 4) << 2;   // 0..60 (s rows within tile)
    const int c0 = (tid & 15) << 2;   // 0..60 (rank cols)

    // fetch mapping: two float4 per buffer per thread
    // v in [0,512): row = v>>3 (0..63), kq = v&7 (k = kq*4)
    const int v0 = tid, v1 = tid + 256;
    const int xrow0 = v0 >> 3, xk0 = (v0 & 7) << 2;
    const int xrow1 = v1 >> 3, xk1 = (v1 & 7) << 2;

    const float* xg = x + ((size_t)b * S_ + s0) * DIN_;
    const float* wg = embed + (size_t)b * EMB_STRIDE_;   // w_down rows: r*DIN + d

    unsigned long long acc[4][2];
#pragma unroll
    for (int i = 0; i < 4; ++i) { acc[i][0] = 0ull; acc[i][1] = 0ull; }

    float4 fx0, fx1, fw0, fw1;
    // prefetch k-tile 0
    fx0 = *(const float4*)(xg + (size_t)xrow0 * DIN_ + xk0);
    fx1 = *(const float4*)(xg + (size_t)xrow1 * DIN_ + xk1);
    fw0 = *(const float4*)(wg + (size_t)xrow0 * DIN_ + xk0);
    fw1 = *(const float4*)(wg + (size_t)xrow1 * DIN_ + xk1);

    const int NKT = DIN_ / KT;  // 40
    for (int kt = 0; kt < NKT; ++kt) {
        __syncthreads();  // previous compute done before overwrite
        // store fetched regs into K-transposed smem
        Xs[xk0 + 0][xrow0] = fx0.x; Xs[xk0 + 1][xrow0] = fx0.y;
        Xs[xk0 + 2][xrow0] = fx0.z; Xs[xk0 + 3][xrow0] = fx0.w;
        Xs[xk1 + 0][xrow1] = fx1.x; Xs[xk1 + 1][xrow1] = fx1.y;
        Xs[xk1 + 2][xrow1] = fx1.z; Xs[xk1 + 3][xrow1] = fx1.w;
        Ws[xk0 + 0][xrow0] = fw0.x; Ws[xk0 + 1][xrow0] = fw0.y;
        Ws[xk0 + 2][xrow0] = fw0.z; Ws[xk0 + 3][xrow0] = fw0.w;
        Ws[xk1 + 0][xrow1] = fw1.x; Ws[xk1 + 1][xrow1] = fw1.y;
        Ws[xk1 + 2][xrow1] = fw1.z; Ws[xk1 + 3][xrow1] = fw1.w;
        __syncthreads();

        // issue next tile's LDGs early so DRAM latency hides under compute
        if (kt + 1 < NKT) {
            const int ko = (kt + 1) * KT;
            fx0 = *(const float4*)(xg + (size_t)xrow0 * DIN_ + ko + xk0);
            fx1 = *(const float4*)(xg + (size_t)xrow1 * DIN_ + ko + xk1);
            fw0 = *(const float4*)(wg + (size_t)xrow0 * DIN_ + ko + xk0);
            fw1 = *(const float4*)(wg + (size_t)xrow1 * DIN_ + ko + xk1);
        }

#pragma unroll
        for (int kk = 0; kk < KT; ++kk) {
            float4 av = *(const float4*)&Xs[kk][r0];
            float4 bv = *(const float4*)&Ws[kk][c0];
            unsigned long long b01 = pack2(bv.x, bv.y);
            unsigned long long b23 = pack2(bv.z, bv.w);
            unsigned long long a;
            a = pack2(av.x, av.x);
            acc[0][0] = fma2(a, b01, acc[0][0]); acc[0][1] = fma2(a, b23, acc[0][1]);
            a = pack2(av.y, av.y);
            acc[1][0] = fma2(a, b01, acc[1][0]); acc[1][1] = fma2(a, b23, acc[1][1]);
            a = pack2(av.z, av.z);
            acc[2][0] = fma2(a, b01, acc[2][0]); acc[2][1] = fma2(a, b23, acc[2][1]);
            a = pack2(av.w, av.w);
            acc[3][0] = fma2(a, b01, acc[3][0]); acc[3][1] = fma2(a, b23, acc[3][1]);
        }
    }

    // epilogue: write h
#pragma unroll
    for (int i = 0; i < 4; ++i) {
        float4 o;
        unpack2(acc[i][0], o.x, o.y);
        unpack2(acc[i][1], o.z, o.w);
        *(float4*)&g_h[((size_t)b * S_ + (s0 + r0 + i)) * RANK_ + c0] = o;
    }
}

// =====================================================================
// Stage 2: out[b,s,o] = sum_r h[b,s,r] * w_up[b,o,r]
// Per-batch GEMM M=1024 (s), N=1280 (o), K=64 (r) — K fits entirely in smem.
// CTA tile: 64(M) x 64(N) x 64(K). Grid: (DOUT/64, S/64, B) = (20,16,8).
// =====================================================================
__global__ __launch_bounds__(256, 4)
void stage2_kernel(const float* __restrict__ embed, float* __restrict__ out) {
    __shared__ float Hs[RANK_][64];   // [k][m]
    __shared__ float Us[RANK_][64];   // [k][n]

    const int tid = threadIdx.x;
    const int b   = blockIdx.z;
    const int s0  = blockIdx.y * 64;
    const int o0  = blockIdx.x * 64;

    const int r0 = (tid >> 4) << 2;
    const int c0 = (tid & 15) << 2;

    // load tiles: 64 rows x 64 k-floats each = 1024 float4 per tile, 4/thread
    const float* hg = g_h + ((size_t)b * S_ + s0) * RANK_;
    const float* ug = embed + (size_t)b * EMB_STRIDE_ + DOWN_SIZE_ + (size_t)o0 * RANK_;

#pragma unroll
    for (int i = 0; i < 4; ++i) {
        int v = tid + i * 256;           // 0..1023
        int row = v >> 4;                // 0..63
        int k   = (v & 15) << 2;         // 0..60
        float4 fh = *(const float4*)(hg + (size_t)row * RANK_ + k);
        float4 fu = *(const float4*)(ug + (size_t)row * RANK_ + k);
        Hs[k + 0][row] = fh.x; Hs[k + 1][row] = fh.y;
        Hs[k + 2][row] = fh.z; Hs[k + 3][row] = fh.w;
        Us[k + 0][row] = fu.x; Us[k + 1][row] = fu.y;
        Us[k + 2][row] = fu.z; Us[k + 3][row] = fu.w;
    }
    __syncthreads();

    unsigned long long acc[4][2];
#pragma unroll
    for (int i = 0; i < 4; ++i) { acc[i][0] = 0ull; acc[i][1] = 0ull; }

#pragma unroll 16
    for (int kk = 0; kk < RANK_; ++kk) {
        float4 av = *(const float4*)&Hs[kk][r0];
        float4 bv = *(const float4*)&Us[kk][c0];
        unsigned long long b01 = pack2(bv.x, bv.y);
        unsigned long long b23 = pack2(bv.z, bv.w);
        unsigned long long a;
        a = pack2(av.x, av.x);
        acc[0][0] = fma2(a, b01, acc[0][0]); acc[0][1] = fma2(a, b23, acc[0][1]);
        a = pack2(av.y, av.y);
        acc[1][0] = fma2(a, b01, acc[1][0]); acc[1][1] = fma2(a, b23, acc[1][1]);
        a = pack2(av.z, av.z);
        acc[2][0] = fma2(a, b01, acc[2][0]); acc[2][1] = fma2(a, b23, acc[2][1]);
        a = pack2(av.w, av.w);
        acc[3][0] = fma2(a, b01, acc[3][0]); acc[3][1] = fma2(a, b23, acc[3][1]);
    }

#pragma unroll
    for (int i = 0; i < 4; ++i) {
        float4 o;
        unpack2(acc[i][0], o.x, o.y);
        unpack2(acc[i][1], o.z, o.w);
        *(float4*)&out[((size_t)b * S_ + (s0 + r0 + i)) * DOUT_ + o0 + c0] = o;
    }
}

extern "C" void kernel_launch(void* const* d_in, const int* in_sizes, int n_in,
                              void* d_out, int out_size) {
    const float* x     = (const float*)d_in[0];   // [8,1024,1280] f32
    const float* embed = (const float*)d_in[1];   // [8,163840]    f32
    float* out = (float*)d_out;                   // [8,1024,1280] f32

    stage1_kernel<<<dim3(S_ / 64, B_), 256>>>(x, embed);
    stage2_kernel<<<dim3(DOUT_ / 64, S_ / 64, B_), 256>>>(embed, out);
}

// round 4
// speedup vs baseline: 1.3496x; 1.3496x over previous
#include <cuda_runtime.h>
#include <cstdint>

// Problem constants
#define B_    8
#define S_    1024
#define DIN_  1280
#define RANK_ 64
#define DOUT_ 1280
#define DOWN_SIZE_ 81920   // RANK*DIN
#define EMB_STRIDE_ 163840 // DOWN_SIZE + UP_SIZE

#define KSPLIT 2
#define KHALF  (DIN_ / KSPLIT)   // 640
#define KT     16

// split-K partial h buffers: h = g_hp[0] + g_hp[1]
__device__ float g_hp[KSPLIT][B_ * S_ * RANK_];

// ---------------- f32x2 helpers (Blackwell packed fp32) ----------------
__device__ __forceinline__ unsigned long long pack2(float lo, float hi) {
    unsigned long long r;
    asm("mov.b64 %0, {%1, %2};" : "=l"(r) : "f"(lo), "f"(hi));
    return r;
}
__device__ __forceinline__ unsigned long long fma2(unsigned long long a,
                                                   unsigned long long b,
                                                   unsigned long long c) {
    unsigned long long d;
    asm("fma.rn.f32x2 %0, %1, %2, %3;" : "=l"(d) : "l"(a), "l"(b), "l"(c));
    return d;
}
__device__ __forceinline__ void unpack2(unsigned long long v, float& lo, float& hi) {
    asm("mov.b64 {%0, %1}, %2;" : "=f"(lo), "=f"(hi) : "l"(v));
}

// Shared inner product update: 8 a-values x (two float4 halves of b) -> acc[8][4]
__device__ __forceinline__ void mm_step(const float a[8],
                                        const float4& bl, const float4& bh,
                                        unsigned long long acc[8][4]) {
    unsigned long long bl01 = pack2(bl.x, bl.y);
    unsigned long long bl23 = pack2(bl.z, bl.w);
    unsigned long long bh01 = pack2(bh.x, bh.y);
    unsigned long long bh23 = pack2(bh.z, bh.w);
#pragma unroll
    for (int i = 0; i < 8; ++i) {
        unsigned long long ad = pack2(a[i], a[i]);
        acc[i][0] = fma2(ad, bl01, acc[i][0]);
        acc[i][1] = fma2(ad, bl23, acc[i][1]);
        acc[i][2] = fma2(ad, bh01, acc[i][2]);
        acc[i][3] = fma2(ad, bh23, acc[i][3]);
    }
}

// =====================================================================
// Stage 1: h[b,s,r] = sum_d x[b,s,d] * w_down[b,r,d]
// CTA tile 128(M=s) x 64(N=r), K split in 2 (640 each), KT=16.
// 128 threads, 8x8 per thread (N as two float4 halves n0 / n0+32).
// Grid (8 s-tiles, 2 k-splits, 8 b) = 128 CTAs -> one full wave.
// =====================================================================
__global__ __launch_bounds__(128)
void stage1_kernel(const float* __restrict__ x, const float* __restrict__ embed) {
    __shared__ __align__(16) float Xs[KT][132];   // [k][m], padded
    __shared__ __align__(16) float Ws[KT][68];    // [k][n], padded

    const int tid = threadIdx.x;
    const int b   = blockIdx.z;
    const int ks  = blockIdx.y;
    const int s0  = blockIdx.x * 128;
    const int kbase = ks * KHALF;

    const int m0 = (tid >> 3) << 3;   // 0..120
    const int n0 = (tid & 7) << 2;    // 0..28 (second half at +32)

    const float* xg = x + ((size_t)b * S_ + s0) * DIN_ + kbase;
    const float* wg = embed + (size_t)b * EMB_STRIDE_ + kbase;

    // fetch mapping
    // A: 512 float4 per ktile -> 4/thread ; B: 256 float4 -> 2/thread
    int arow[4], akq[4], brow[2], bkq[2];
#pragma unroll
    for (int t = 0; t < 4; ++t) { int idx = tid + t * 128; arow[t] = idx >> 2; akq[t] = (idx & 3) << 2; }
#pragma unroll
    for (int t = 0; t < 2; ++t) { int idx = tid + t * 128; brow[t] = idx >> 2; bkq[t] = (idx & 3) << 2; }

    unsigned long long acc[8][4];
#pragma unroll
    for (int i = 0; i < 8; ++i)
#pragma unroll
        for (int j = 0; j < 4; ++j) acc[i][j] = 0ull;

    float4 pa[4], pb[2];
#pragma unroll
    for (int t = 0; t < 4; ++t) pa[t] = *(const float4*)(xg + (size_t)arow[t] * DIN_ + akq[t]);
#pragma unroll
    for (int t = 0; t < 2; ++t) pb[t] = *(const float4*)(wg + (size_t)brow[t] * DIN_ + bkq[t]);

    const int NKT = KHALF / KT;   // 40
    for (int kt = 0; kt < NKT; ++kt) {
        __syncthreads();
#pragma unroll
        for (int t = 0; t < 4; ++t) {
            Xs[akq[t] + 0][arow[t]] = pa[t].x;
            Xs[akq[t] + 1][arow[t]] = pa[t].y;
            Xs[akq[t] + 2][arow[t]] = pa[t].z;
            Xs[akq[t] + 3][arow[t]] = pa[t].w;
        }
#pragma unroll
        for (int t = 0; t < 2; ++t) {
            Ws[bkq[t] + 0][brow[t]] = pb[t].x;
            Ws[bkq[t] + 1][brow[t]] = pb[t].y;
            Ws[bkq[t] + 2][brow[t]] = pb[t].z;
            Ws[bkq[t] + 3][brow[t]] = pb[t].w;
        }
        __syncthreads();

        if (kt + 1 < NKT) {
            const int ko = (kt + 1) * KT;
#pragma unroll
            for (int t = 0; t < 4; ++t) pa[t] = *(const float4*)(xg + (size_t)arow[t] * DIN_ + ko + akq[t]);
#pragma unroll
            for (int t = 0; t < 2; ++t) pb[t] = *(const float4*)(wg + (size_t)brow[t] * DIN_ + ko + bkq[t]);
        }

#pragma unroll
        for (int kk = 0; kk < KT; ++kk) {
            float4 a0 = *(const float4*)&Xs[kk][m0];
            float4 a1 = *(const float4*)&Xs[kk][m0 + 4];
            float4 bl = *(const float4*)&Ws[kk][n0];
            float4 bh = *(const float4*)&Ws[kk][n0 + 32];
            float a[8] = {a0.x, a0.y, a0.z, a0.w, a1.x, a1.y, a1.z, a1.w};
            mm_step(a, bl, bh, acc);
        }
    }

    float* hout = &g_hp[ks][((size_t)b * S_ + s0) * RANK_];
#pragma unroll
    for (int i = 0; i < 8; ++i) {
        float4 lo, hi;
        unpack2(acc[i][0], lo.x, lo.y);
        unpack2(acc[i][1], lo.z, lo.w);
        unpack2(acc[i][2], hi.x, hi.y);
        unpack2(acc[i][3], hi.z, hi.w);
        *(float4*)(hout + (size_t)(m0 + i) * RANK_ + n0)      = lo;
        *(float4*)(hout + (size_t)(m0 + i) * RANK_ + n0 + 32) = hi;
    }
}

// =====================================================================
// Stage 2: out[b,s,o] = sum_r (h0+h1)[b,s,r] * w_up[b,o,r]
// CTA tile 128(M=s) x 64(N=o), K=64 in 4 ktiles of 16.
// 128 threads, 8x8 per thread. Grid (20, 8, 8) = 1280 CTAs.
// =====================================================================
__global__ __launch_bounds__(128)
void stage2_kernel(const float* __restrict__ embed, float* __restrict__ out) {
    __shared__ __align__(16) float Hs[KT][132];
    __shared__ __align__(16) float Us[KT][68];

    const int tid = threadIdx.x;
    const int b   = blockIdx.z;
    const int s0  = blockIdx.y * 128;
    const int o0  = blockIdx.x * 64;

    const int m0 = (tid >> 3) << 3;
    const int n0 = (tid & 7) << 2;

    const float* h0 = &g_hp[0][((size_t)b * S_ + s0) * RANK_];
    const float* h1 = &g_hp[1][((size_t)b * S_ + s0) * RANK_];
    const float* ug = embed + (size_t)b * EMB_STRIDE_ + DOWN_SIZE_ + (size_t)o0 * RANK_;

    int arow[4], akq[4], brow[2], bkq[2];
#pragma unroll
    for (int t = 0; t < 4; ++t) { int idx = tid + t * 128; arow[t] = idx >> 2; akq[t] = (idx & 3) << 2; }
#pragma unroll
    for (int t = 0; t < 2; ++t) { int idx = tid + t * 128; brow[t] = idx >> 2; bkq[t] = (idx & 3) << 2; }

    unsigned long long acc[8][4];
#pragma unroll
    for (int i = 0; i < 8; ++i)
#pragma unroll
        for (int j = 0; j < 4; ++j) acc[i][j] = 0ull;

    float4 pa0[4], pa1[4], pb[2];
#pragma unroll
    for (int t = 0; t < 4; ++t) {
        pa0[t] = *(const float4*)(h0 + (size_t)arow[t] * RANK_ + akq[t]);
        pa1[t] = *(const float4*)(h1 + (size_t)arow[t] * RANK_ + akq[t]);
    }
#pragma unroll
    for (int t = 0; t < 2; ++t) pb[t] = *(const float4*)(ug + (size_t)brow[t] * RANK_ + bkq[t]);

    const int NKT = RANK_ / KT;  // 4
    for (int kt = 0; kt < NKT; ++kt) {
        __syncthreads();
#pragma unroll
        for (int t = 0; t < 4; ++t) {
            Hs[akq[t] + 0][arow[t]] = pa0[t].x + pa1[t].x;
            Hs[akq[t] + 1][arow[t]] = pa0[t].y + pa1[t].y;
            Hs[akq[t] + 2][arow[t]] = pa0[t].z + pa1[t].z;
            Hs[akq[t] + 3][arow[t]] = pa0[t].w + pa1[t].w;
        }
#pragma unroll
        for (int t = 0; t < 2; ++t) {
            Us[bkq[t] + 0][brow[t]] = pb[t].x;
            Us[bkq[t] + 1][brow[t]] = pb[t].y;
            Us[bkq[t] + 2][brow[t]] = pb[t].z;
            Us[bkq[t] + 3][brow[t]] = pb[t].w;
        }
        __syncthreads();

        if (kt + 1 < NKT) {
            const int ko = (kt + 1) * KT;
#pragma unroll
            for (int t = 0; t < 4; ++t) {
                pa0[t] = *(const float4*)(h0 + (size_t)arow[t] * RANK_ + ko + akq[t]);
                pa1[t] = *(const float4*)(h1 + (size_t)arow[t] * RANK_ + ko + akq[t]);
            }
#pragma unroll
            for (int t = 0; t < 2; ++t) pb[t] = *(const float4*)(ug + (size_t)brow[t] * RANK_ + ko + bkq[t]);
        }

#pragma unroll
        for (int kk = 0; kk < KT; ++kk) {
            float4 a0 = *(const float4*)&Hs[kk][m0];
            float4 a1 = *(const float4*)&Hs[kk][m0 + 4];
            float4 bl = *(const float4*)&Us[kk][n0];
            float4 bh = *(const float4*)&Us[kk][n0 + 32];
            float a[8] = {a0.x, a0.y, a0.z, a0.w, a1.x, a1.y, a1.z, a1.w};
            mm_step(a, bl, bh, acc);
        }
    }

    float* og = out + ((size_t)b * S_ + s0) * DOUT_ + o0;
#pragma unroll
    for (int i = 0; i < 8; ++i) {
        float4 lo, hi;
        unpack2(acc[i][0], lo.x, lo.y);
        unpack2(acc[i][1], lo.z, lo.w);
        unpack2(acc[i][2], hi.x, hi.y);
        unpack2(acc[i][3], hi.z, hi.w);
        *(float4*)(og + (size_t)(m0 + i) * DOUT_ + n0)      = lo;
        *(float4*)(og + (size_t)(m0 + i) * DOUT_ + n0 + 32) = hi;
    }
}

extern "C" void kernel_launch(void* const* d_in, const int* in_sizes, int n_in,
                              void* d_out, int out_size) {
    const float* x     = (const float*)d_in[0];   // [8,1024,1280] f32
    const float* embed = (const float*)d_in[1];   // [8,163840]    f32
    float* out = (float*)d_out;                   // [8,1024,1280] f32

    stage1_kernel<<<dim3(S_ / 128, KSPLIT, B_), 128>>>(x, embed);
    stage2_kernel<<<dim3(DOUT_ / 64, S_ / 128, B_), 128>>>(embed, out);
}

// round 8
// speedup vs baseline: 2.6331x; 1.9509x over previous
#include <cuda_runtime.h>
#include <cstdint>

// ---------------- problem constants ----------------
#define B_    8
#define S_    1024
#define DIN_  1280
#define RANK_ 64
#define DOUT_ 1280
#define DOWN_SIZE_ 81920
#define EMB_STRIDE_ 163840

#define KSPLIT 2
#define KHALF_ 640
#define NCHUNK1 20          // KHALF_/32 for stage 1
#define NCHUNK2 2           // RANK_/32 for stage 2

// smem row stride: 32 data bf16 + 8 pad = 40 elems = 80 bytes (conflict-free ldmatrix)
#define SA  40
#define SAB 80

// split-K fp32 partial h buffers
__device__ float g_hp[KSPLIT][B_ * S_ * RANK_];

// ---------------- helpers ----------------
__device__ __forceinline__ uint32_t smem_u32(const void* p) {
    uint32_t a;
    asm("{ .reg .u64 t; cvta.to.shared.u64 t, %1; cvt.u32.u64 %0, t; }" : "=r"(a) : "l"(p));
    return a;
}

// fp32x4 -> packed bf16x2 hi pair + lo pair (low 16 bits = lower k index)
__device__ __forceinline__ void split4(const float4 v, uint32_t& h01, uint32_t& h23,
                                       uint32_t& l01, uint32_t& l23) {
    asm("cvt.rn.bf16x2.f32 %0, %1, %2;" : "=r"(h01) : "f"(v.y), "f"(v.x));
    asm("cvt.rn.bf16x2.f32 %0, %1, %2;" : "=r"(h23) : "f"(v.w), "f"(v.z));
    float r0 = v.x - __uint_as_float(h01 << 16);
    float r1 = v.y - __uint_as_float(h01 & 0xFFFF0000u);
    float r2 = v.z - __uint_as_float(h23 << 16);
    float r3 = v.w - __uint_as_float(h23 & 0xFFFF0000u);
    asm("cvt.rn.bf16x2.f32 %0, %1, %2;" : "=r"(l01) : "f"(r1), "f"(r0));
    asm("cvt.rn.bf16x2.f32 %0, %1, %2;" : "=r"(l23) : "f"(r3), "f"(r2));
}

__device__ __forceinline__ void ldsm4(uint32_t addr, uint32_t& r0, uint32_t& r1,
                                      uint32_t& r2, uint32_t& r3) {
    asm volatile("ldmatrix.sync.aligned.m8n8.x4.shared.b16 {%0,%1,%2,%3}, [%4];"
                 : "=r"(r0), "=r"(r1), "=r"(r2), "=r"(r3) : "r"(addr));
}

__device__ __forceinline__ void mma16816(float d[4], const uint32_t a[4],
                                         uint32_t b0, uint32_t b1) {
    asm volatile("mma.sync.aligned.m16n8k16.row.col.f32.bf16.bf16.f32 "
                 "{%0,%1,%2,%3}, {%4,%5,%6,%7}, {%8,%9}, {%0,%1,%2,%3};"
                 : "+f"(d[0]), "+f"(d[1]), "+f"(d[2]), "+f"(d[3])
                 : "r"(a[0]), "r"(a[1]), "r"(a[2]), "r"(a[3]), "r"(b0), "r"(b1));
}

// One k16 step for a 32x32 warp tile, 3-term bf16-split accumulation.
// ah/al/bh/bl: smem byte addresses of this warp's tile origin at this k16.
__device__ __forceinline__ void k16_compute(uint32_t ah, uint32_t al,
                                            uint32_t bh, uint32_t bl,
                                            uint32_t a_off, uint32_t b_off,
                                            float acc[2][4][4]) {
    uint32_t Ah[2][4], Al[2][4], Bh[4][2], Bl[4][2];
    ldsm4(ah + a_off,            Ah[0][0], Ah[0][1], Ah[0][2], Ah[0][3]);
    ldsm4(ah + 16 * SAB + a_off, Ah[1][0], Ah[1][1], Ah[1][2], Ah[1][3]);
    ldsm4(al + a_off,            Al[0][0], Al[0][1], Al[0][2], Al[0][3]);
    ldsm4(al + 16 * SAB + a_off, Al[1][0], Al[1][1], Al[1][2], Al[1][3]);
    ldsm4(bh + b_off,            Bh[0][0], Bh[0][1], Bh[1][0], Bh[1][1]);
    ldsm4(bh + 16 * SAB + b_off, Bh[2][0], Bh[2][1], Bh[3][0], Bh[3][1]);
    ldsm4(bl + b_off,            Bl[0][0], Bl[0][1], Bl[1][0], Bl[1][1]);
    ldsm4(bl + 16 * SAB + b_off, Bl[2][0], Bl[2][1], Bl[3][0], Bl[3][1]);
#pragma unroll
    for (int t = 0; t < 2; ++t)
#pragma unroll
        for (int n = 0; n < 4; ++n) {
            mma16816(acc[t][n], Ah[t], Bh[n][0], Bh[n][1]);
            mma16816(acc[t][n], Ah[t], Bl[n][0], Bl[n][1]);
            mma16816(acc[t][n], Al[t], Bh[n][0], Bh[n][1]);
        }
}

// lane-dependent ldmatrix address offsets (bytes)
__device__ __forceinline__ uint32_t a_lane_off(int lane) {
    return (uint32_t)((lane & 15) * SAB + (lane >> 4) * 16);
}
__device__ __forceinline__ uint32_t b_lane_off(int lane) {
    return (uint32_t)(((((lane >> 4) << 3) + (lane & 7))) * SAB + ((lane >> 3) & 1) * 16);
}

// =====================================================================
// Stage 1: h_partial[ks][b,s,r] = sum_{d in half ks} x[b,s,d]*w_down[b,r,d]
// CTA tile 128(M=s) x 64(N=r); K=640 in 20 chunks of 32; grid (8,2,8)=128.
// =====================================================================
__global__ __launch_bounds__(256, 1)
void stage1_kernel(const float* __restrict__ x, const float* __restrict__ embed) {
    __shared__ __align__(16) uint16_t AhS[128][SA], AlS[128][SA];
    __shared__ __align__(16) uint16_t BhS[64][SA],  BlS[64][SA];

    const int tid = threadIdx.x, lane = tid & 31, wid = tid >> 5;
    const int warp_m = wid >> 1, warp_n = wid & 1;
    const int b = blockIdx.z, ks = blockIdx.y, s0 = blockIdx.x * 128;

    const float* xg = x + ((size_t)b * S_ + s0) * DIN_ + ks * KHALF_;
    const float* wg = embed + (size_t)b * EMB_STRIDE_ + ks * KHALF_;

    const uint32_t ahb = smem_u32(AhS), alb = smem_u32(AlS);
    const uint32_t bhb = smem_u32(BhS), blb = smem_u32(BlS);
    const uint32_t a_off = a_lane_off(lane);
    const uint32_t b_off = b_lane_off(lane);
    const uint32_t awm = (uint32_t)(warp_m * 32 * SAB);
    const uint32_t bwn = (uint32_t)(warp_n * 32 * SAB);

    // loaders: A 128x32 f32 = 1024 float4 (4/thr); B 64x32 = 512 float4 (2/thr)
    int arow[4], ac4[4], brow[2], bc4[2];
#pragma unroll
    for (int i = 0; i < 4; ++i) { int id = tid + i * 256; arow[i] = id >> 3; ac4[i] = (id & 7) << 2; }
#pragma unroll
    for (int i = 0; i < 2; ++i) { int id = tid + i * 256; brow[i] = id >> 3; bc4[i] = (id & 7) << 2; }

    float acc[2][4][4];
#pragma unroll
    for (int t = 0; t < 2; ++t)
#pragma unroll
        for (int n = 0; n < 4; ++n)
#pragma unroll
            for (int j = 0; j < 4; ++j) acc[t][n][j] = 0.f;

    float4 va[4], vb[2];
#pragma unroll
    for (int i = 0; i < 4; ++i) va[i] = *(const float4*)(xg + (size_t)arow[i] * DIN_ + ac4[i]);
#pragma unroll
    for (int i = 0; i < 2; ++i) vb[i] = *(const float4*)(wg + (size_t)brow[i] * DIN_ + bc4[i]);

    for (int c = 0; c < NCHUNK1; ++c) {
        __syncthreads();  // previous chunk's compute finished
#pragma unroll
        for (int i = 0; i < 4; ++i) {
            uint32_t h01, h23, l01, l23;
            split4(va[i], h01, h23, l01, l23);
            uint32_t off = (uint32_t)(arow[i] * SAB + ac4[i] * 2);
            *(uint2*)((char*)AhS + off) = make_uint2(h01, h23);
            *(uint2*)((char*)AlS + off) = make_uint2(l01, l23);
        }
#pragma unroll
        for (int i = 0; i < 2; ++i) {
            uint32_t h01, h23, l01, l23;
            split4(vb[i], h01, h23, l01, l23);
            uint32_t off = (uint32_t)(brow[i] * SAB + bc4[i] * 2);
            *(uint2*)((char*)BhS + off) = make_uint2(h01, h23);
            *(uint2*)((char*)BlS + off) = make_uint2(l01, l23);
        }
        __syncthreads();

        if (c + 1 < NCHUNK1) {
            const int ko = (c + 1) * 32;
#pragma unroll
            for (int i = 0; i < 4; ++i) va[i] = *(const float4*)(xg + (size_t)arow[i] * DIN_ + ko + ac4[i]);
#pragma unroll
            for (int i = 0; i < 2; ++i) vb[i] = *(const float4*)(wg + (size_t)brow[i] * DIN_ + ko + bc4[i]);
        }

        k16_compute(ahb + awm,      alb + awm,      bhb + bwn,      blb + bwn,      a_off, b_off, acc);
        k16_compute(ahb + awm + 32, alb + awm + 32, bhb + bwn + 32, blb + bwn + 32, a_off, b_off, acc);
    }

    // epilogue -> g_hp[ks]
    float* hp = g_hp[ks] + ((size_t)b * S_ + s0) * RANK_;
#pragma unroll
    for (int t = 0; t < 2; ++t)
#pragma unroll
        for (int n8 = 0; n8 < 4; ++n8) {
            int m = warp_m * 32 + t * 16 + (lane >> 2);
            int n = warp_n * 32 + n8 * 8 + (lane & 3) * 2;
            *(float2*)(hp + (size_t)m * RANK_ + n)       = make_float2(acc[t][n8][0], acc[t][n8][1]);
            *(float2*)(hp + (size_t)(m + 8) * RANK_ + n) = make_float2(acc[t][n8][2], acc[t][n8][3]);
        }
}

// =====================================================================
// Stage 2: out[b,s,o] = sum_r (h0+h1)[b,s,r] * w_up[b,o,r]
// CTA tile 128(M=s) x 64(N=o); K=64 in 2 chunks of 32; grid (20,8,8)=1280.
// =====================================================================
__global__ __launch_bounds__(256, 2)
void stage2_kernel(const float* __restrict__ embed, float* __restrict__ out) {
    __shared__ __align__(16) uint16_t AhS[128][SA], AlS[128][SA];
    __shared__ __align__(16) uint16_t BhS[64][SA],  BlS[64][SA];

    const int tid = threadIdx.x, lane = tid & 31, wid = tid >> 5;
    const int warp_m = wid >> 1, warp_n = wid & 1;
    const int b = blockIdx.z, s0 = blockIdx.y * 128, o0 = blockIdx.x * 64;

    const float* h0 = g_hp[0] + ((size_t)b * S_ + s0) * RANK_;
    const float* h1 = g_hp[1] + ((size_t)b * S_ + s0) * RANK_;
    const float* ug = embed + (size_t)b * EMB_STRIDE_ + DOWN_SIZE_ + (size_t)o0 * RANK_;

    const uint32_t ahb = smem_u32(AhS), alb = smem_u32(AlS);
    const uint32_t bhb = smem_u32(BhS), blb = smem_u32(BlS);
    const uint32_t a_off = a_lane_off(lane);
    const uint32_t b_off = b_lane_off(lane);
    const uint32_t awm = (uint32_t)(warp_m * 32 * SAB);
    const uint32_t bwn = (uint32_t)(warp_n * 32 * SAB);

    int arow[4], ac4[4], brow[2], bc4[2];
#pragma unroll
    for (int i = 0; i < 4; ++i) { int id = tid + i * 256; arow[i] = id >> 3; ac4[i] = (id & 7) << 2; }
#pragma unroll
    for (int i = 0; i < 2; ++i) { int id = tid + i * 256; brow[i] = id >> 3; bc4[i] = (id & 7) << 2; }

    float acc[2][4][4];
#pragma unroll
    for (int t = 0; t < 2; ++t)
#pragma unroll
        for (int n = 0; n < 4; ++n)
#pragma unroll
            for (int j = 0; j < 4; ++j) acc[t][n][j] = 0.f;

    float4 va0[4], va1[4], vb[2];
#pragma unroll
    for (int i = 0; i < 4; ++i) {
        va0[i] = *(const float4*)(h0 + (size_t)arow[i] * RANK_ + ac4[i]);
        va1[i] = *(const float4*)(h1 + (size_t)arow[i] * RANK_ + ac4[i]);
    }
#pragma unroll
    for (int i = 0; i < 2; ++i) vb[i] = *(const float4*)(ug + (size_t)brow[i] * RANK_ + bc4[i]);

    for (int c = 0; c < NCHUNK2; ++c) {
        __syncthreads();
#pragma unroll
        for (int i = 0; i < 4; ++i) {
            float4 v;
            v.x = va0[i].x + va1[i].x; v.y = va0[i].y + va1[i].y;
            v.z = va0[i].z + va1[i].z; v.w = va0[i].w + va1[i].w;
            uint32_t h01, h23, l01, l23;
            split4(v, h01, h23, l01, l23);
            uint32_t off = (uint32_t)(arow[i] * SAB + ac4[i] * 2);
            *(uint2*)((char*)AhS + off) = make_uint2(h01, h23);
            *(uint2*)((char*)AlS + off) = make_uint2(l01, l23);
        }
#pragma unroll
        for (int i = 0; i < 2; ++i) {
            uint32_t h01, h23, l01, l23;
            split4(vb[i], h01, h23, l01, l23);
            uint32_t off = (uint32_t)(brow[i] * SAB + bc4[i] * 2);
            *(uint2*)((char*)BhS + off) = make_uint2(h01, h23);
            *(uint2*)((char*)BlS + off) = make_uint2(l01, l23);
        }
        __syncthreads();

        if (c + 1 < NCHUNK2) {
            const int ko = (c + 1) * 32;
#pragma unroll
            for (int i = 0; i < 4; ++i) {
                va0[i] = *(const float4*)(h0 + (size_t)arow[i] * RANK_ + ko + ac4[i]);
                va1[i] = *(const float4*)(h1 + (size_t)arow[i] * RANK_ + ko + ac4[i]);
            }
#pragma unroll
            for (int i = 0; i < 2; ++i) vb[i] = *(const float4*)(ug + (size_t)brow[i] * RANK_ + ko + bc4[i]);
        }

        k16_compute(ahb + awm,      alb + awm,      bhb + bwn,      blb + bwn,      a_off, b_off, acc);
        k16_compute(ahb + awm + 32, alb + awm + 32, bhb + bwn + 32, blb + bwn + 32, a_off, b_off, acc);
    }

    // epilogue -> out
    float* og = out + ((size_t)b * S_ + s0) * DOUT_ + o0;
#pragma unroll
    for (int t = 0; t < 2; ++t)
#pragma unroll
        for (int n8 = 0; n8 < 4; ++n8) {
            int m = warp_m * 32 + t * 16 + (lane >> 2);
            int n = warp_n * 32 + n8 * 8 + (lane & 3) * 2;
            *(float2*)(og + (size_t)m * DOUT_ + n)       = make_float2(acc[t][n8][0], acc[t][n8][1]);
            *(float2*)(og + (size_t)(m + 8) * DOUT_ + n) = make_float2(acc[t][n8][2], acc[t][n8][3]);
        }
}

extern "C" void kernel_launch(void* const* d_in, const int* in_sizes, int n_in,
                              void* d_out, int out_size) {
    const float* x     = (const float*)d_in[0];   // [8,1024,1280] f32
    const float* embed = (const float*)d_in[1];   // [8,163840]    f32
    float* out = (float*)d_out;                   // [8,1024,1280] f32

    stage1_kernel<<<dim3(S_ / 128, KSPLIT, B_), 256>>>(x, embed);
    stage2_kernel<<<dim3(DOUT_ / 64, S_ / 128, B_), 256>>>(embed, out);
}

// round 9
// speedup vs baseline: 2.8640x; 1.0877x over previous
#include <cuda_runtime.h>
#include <cstdint>

// ---------------- problem constants ----------------
#define B_    8
#define S_    1024
#define DIN_  1280
#define RANK_ 64
#define DOUT_ 1280
#define DOWN_SIZE_ 81920
#define EMB_STRIDE_ 163840

#define KSPLIT 4
#define KQ_    320          // DIN_/KSPLIT
#define NCHUNK1 10          // KQ_/32

// stage1 smem row stride: 32 data bf16 + 8 pad = 40 elems = 80 B (conflict-free ldmatrix)
#define SA  40
#define SAB 80

// stage2 smem row stride: 64 data bf16 + 8 pad = 72 elems = 144 B (conflict-free)
#define S2A  72
#define S2AB 144

// stage2: o-tiles per CTA
#define NOTILE 4

// split-K fp32 partial h buffers
__device__ float g_hp[KSPLIT][B_ * S_ * RANK_];

// ---------------- helpers ----------------
__device__ __forceinline__ uint32_t smem_u32(const void* p) {
    uint32_t a;
    asm("{ .reg .u64 t; cvta.to.shared.u64 t, %1; cvt.u32.u64 %0, t; }" : "=r"(a) : "l"(p));
    return a;
}

// fp32x4 -> packed bf16x2 hi pair + lo pair (low 16 bits = lower k index)
__device__ __forceinline__ void split4(const float4 v, uint32_t& h01, uint32_t& h23,
                                       uint32_t& l01, uint32_t& l23) {
    asm("cvt.rn.bf16x2.f32 %0, %1, %2;" : "=r"(h01) : "f"(v.y), "f"(v.x));
    asm("cvt.rn.bf16x2.f32 %0, %1, %2;" : "=r"(h23) : "f"(v.w), "f"(v.z));
    float r0 = v.x - __uint_as_float(h01 << 16);
    float r1 = v.y - __uint_as_float(h01 & 0xFFFF0000u);
    float r2 = v.z - __uint_as_float(h23 << 16);
    float r3 = v.w - __uint_as_float(h23 & 0xFFFF0000u);
    asm("cvt.rn.bf16x2.f32 %0, %1, %2;" : "=r"(l01) : "f"(r1), "f"(r0));
    asm("cvt.rn.bf16x2.f32 %0, %1, %2;" : "=r"(l23) : "f"(r3), "f"(r2));
}

__device__ __forceinline__ void ldsm4(uint32_t addr, uint32_t& r0, uint32_t& r1,
                                      uint32_t& r2, uint32_t& r3) {
    asm volatile("ldmatrix.sync.aligned.m8n8.x4.shared.b16 {%0,%1,%2,%3}, [%4];"
                 : "=r"(r0), "=r"(r1), "=r"(r2), "=r"(r3) : "r"(addr));
}

__device__ __forceinline__ void mma16816(float d[4], const uint32_t a[4],
                                         uint32_t b0, uint32_t b1) {
    asm volatile("mma.sync.aligned.m16n8k16.row.col.f32.bf16.bf16.f32 "
                 "{%0,%1,%2,%3}, {%4,%5,%6,%7}, {%8,%9}, {%0,%1,%2,%3};"
                 : "+f"(d[0]), "+f"(d[1]), "+f"(d[2]), "+f"(d[3])
                 : "r"(a[0]), "r"(a[1]), "r"(a[2]), "r"(a[3]), "r"(b0), "r"(b1));
}

// One k16 step for a 32x32 warp tile, 3-term bf16-split. STRIDE = row stride bytes.
template <int STRIDE>
__device__ __forceinline__ void k16_compute(uint32_t ah, uint32_t al,
                                            uint32_t bh, uint32_t bl,
                                            uint32_t a_off, uint32_t b_off,
                                            float acc[2][4][4]) {
    uint32_t Ah[2][4], Al[2][4], Bh[4][2], Bl[4][2];
    ldsm4(ah + a_off,               Ah[0][0], Ah[0][1], Ah[0][2], Ah[0][3]);
    ldsm4(ah + 16 * STRIDE + a_off, Ah[1][0], Ah[1][1], Ah[1][2], Ah[1][3]);
    ldsm4(al + a_off,               Al[0][0], Al[0][1], Al[0][2], Al[0][3]);
    ldsm4(al + 16 * STRIDE + a_off, Al[1][0], Al[1][1], Al[1][2], Al[1][3]);
    ldsm4(bh + b_off,               Bh[0][0], Bh[0][1], Bh[1][0], Bh[1][1]);
    ldsm4(bh + 16 * STRIDE + b_off, Bh[2][0], Bh[2][1], Bh[3][0], Bh[3][1]);
    ldsm4(bl + b_off,               Bl[0][0], Bl[0][1], Bl[1][0], Bl[1][1]);
    ldsm4(bl + 16 * STRIDE + b_off, Bl[2][0], Bl[2][1], Bl[3][0], Bl[3][1]);
#pragma unroll
    for (int t = 0; t < 2; ++t)
#pragma unroll
        for (int n = 0; n < 4; ++n) {
            mma16816(acc[t][n], Ah[t], Bh[n][0], Bh[n][1]);
            mma16816(acc[t][n], Ah[t], Bl[n][0], Bl[n][1]);
            mma16816(acc[t][n], Al[t], Bh[n][0], Bh[n][1]);
        }
}

template <int STRIDE>
__device__ __forceinline__ uint32_t a_lane_off(int lane) {
    return (uint32_t)((lane & 15) * STRIDE + (lane >> 4) * 16);
}
template <int STRIDE>
__device__ __forceinline__ uint32_t b_lane_off(int lane) {
    return (uint32_t)(((((lane >> 4) << 3) + (lane & 7))) * STRIDE + ((lane >> 3) & 1) * 16);
}

// =====================================================================
// Stage 1: h_partial[ks][b,s,r] = sum_{d in quarter ks} x[b,s,d]*w_down[b,r,d]
// CTA 128(M) x 64(N); K=320 in 10 chunks of 32; grid (8,4,8)=256, 2 CTAs/SM.
// =====================================================================
__global__ __launch_bounds__(256, 2)
void stage1_kernel(const float* __restrict__ x, const float* __restrict__ embed) {
    __shared__ __align__(16) uint16_t AhS[128][SA], AlS[128][SA];
    __shared__ __align__(16) uint16_t BhS[64][SA],  BlS[64][SA];

    const int tid = threadIdx.x, lane = tid & 31, wid = tid >> 5;
    const int warp_m = wid >> 1, warp_n = wid & 1;
    const int b = blockIdx.z, ks = blockIdx.y, s0 = blockIdx.x * 128;

    const float* xg = x + ((size_t)b * S_ + s0) * DIN_ + ks * KQ_;
    const float* wg = embed + (size_t)b * EMB_STRIDE_ + ks * KQ_;

    const uint32_t ahb = smem_u32(AhS), alb = smem_u32(AlS);
    const uint32_t bhb = smem_u32(BhS), blb = smem_u32(BlS);
    const uint32_t a_off = a_lane_off<SAB>(lane);
    const uint32_t b_off = b_lane_off<SAB>(lane);
    const uint32_t awm = (uint32_t)(warp_m * 32 * SAB);
    const uint32_t bwn = (uint32_t)(warp_n * 32 * SAB);

    int arow[4], ac4[4], brow[2], bc4[2];
#pragma unroll
    for (int i = 0; i < 4; ++i) { int id = tid + i * 256; arow[i] = id >> 3; ac4[i] = (id & 7) << 2; }
#pragma unroll
    for (int i = 0; i < 2; ++i) { int id = tid + i * 256; brow[i] = id >> 3; bc4[i] = (id & 7) << 2; }

    float acc[2][4][4];
#pragma unroll
    for (int t = 0; t < 2; ++t)
#pragma unroll
        for (int n = 0; n < 4; ++n)
#pragma unroll
            for (int j = 0; j < 4; ++j) acc[t][n][j] = 0.f;

    float4 va[4], vb[2];
#pragma unroll
    for (int i = 0; i < 4; ++i) va[i] = *(const float4*)(xg + (size_t)arow[i] * DIN_ + ac4[i]);
#pragma unroll
    for (int i = 0; i < 2; ++i) vb[i] = *(const float4*)(wg + (size_t)brow[i] * DIN_ + bc4[i]);

    for (int c = 0; c < NCHUNK1; ++c) {
        __syncthreads();
#pragma unroll
        for (int i = 0; i < 4; ++i) {
            uint32_t h01, h23, l01, l23;
            split4(va[i], h01, h23, l01, l23);
            uint32_t off = (uint32_t)(arow[i] * SAB + ac4[i] * 2);
            *(uint2*)((char*)AhS + off) = make_uint2(h01, h23);
            *(uint2*)((char*)AlS + off) = make_uint2(l01, l23);
        }
#pragma unroll
        for (int i = 0; i < 2; ++i) {
            uint32_t h01, h23, l01, l23;
            split4(vb[i], h01, h23, l01, l23);
            uint32_t off = (uint32_t)(brow[i] * SAB + bc4[i] * 2);
            *(uint2*)((char*)BhS + off) = make_uint2(h01, h23);
            *(uint2*)((char*)BlS + off) = make_uint2(l01, l23);
        }
        __syncthreads();

        if (c + 1 < NCHUNK1) {
            const int ko = (c + 1) * 32;
#pragma unroll
            for (int i = 0; i < 4; ++i) va[i] = *(const float4*)(xg + (size_t)arow[i] * DIN_ + ko + ac4[i]);
#pragma unroll
            for (int i = 0; i < 2; ++i) vb[i] = *(const float4*)(wg + (size_t)brow[i] * DIN_ + ko + bc4[i]);
        }

        k16_compute<SAB>(ahb + awm,      alb + awm,      bhb + bwn,      blb + bwn,      a_off, b_off, acc);
        k16_compute<SAB>(ahb + awm + 32, alb + awm + 32, bhb + bwn + 32, blb + bwn + 32, a_off, b_off, acc);
    }

    float* hp = g_hp[ks] + ((size_t)b * S_ + s0) * RANK_;
#pragma unroll
    for (int t = 0; t < 2; ++t)
#pragma unroll
        for (int n8 = 0; n8 < 4; ++n8) {
            int m = warp_m * 32 + t * 16 + (lane >> 2);
            int n = warp_n * 32 + n8 * 8 + (lane & 3) * 2;
            *(float2*)(hp + (size_t)m * RANK_ + n)       = make_float2(acc[t][n8][0], acc[t][n8][1]);
            *(float2*)(hp + (size_t)(m + 8) * RANK_ + n) = make_float2(acc[t][n8][2], acc[t][n8][3]);
        }
}

// =====================================================================
// Stage 2: out[b,s,o] = sum_r (sum_ks h_ks)[b,s,r] * w_up[b,o,r]
// CTA 128(M) x 256(N as 4 o-tiles of 64); K=64 whole in smem.
// A tile built ONCE per CTA; loop 4 o-tiles. grid (5,8,8)=320.
// smem dynamic: Ah(128x72) Al Bh(64x72) Bl bf16 = 54 KB.
// =====================================================================
#define S2_AH 0
#define S2_AL (128 * S2AB)                 // 18432
#define S2_BH (2 * 128 * S2AB)             // 36864
#define S2_BL (2 * 128 * S2AB + 64 * S2AB) // 46080
#define S2_SMEM (2 * 128 * S2AB + 2 * 64 * S2AB)  // 55296

__global__ __launch_bounds__(256, 2)
void stage2_kernel(const float* __restrict__ embed, float* __restrict__ out) {
    extern __shared__ __align__(16) char smem2[];
    const uint32_t sbase = smem_u32(smem2);

    const int tid = threadIdx.x, lane = tid & 31, wid = tid >> 5;
    const int warp_m = wid >> 1, warp_n = wid & 1;
    const int b = blockIdx.z, s0 = blockIdx.y * 128, og0 = blockIdx.x * (NOTILE * 64);

    const float* h0 = g_hp[0] + ((size_t)b * S_ + s0) * RANK_;
    const float* h1 = g_hp[1] + ((size_t)b * S_ + s0) * RANK_;
    const float* h2 = g_hp[2] + ((size_t)b * S_ + s0) * RANK_;
    const float* h3 = g_hp[3] + ((size_t)b * S_ + s0) * RANK_;
    const float* ug = embed + (size_t)b * EMB_STRIDE_ + DOWN_SIZE_ + (size_t)og0 * RANK_;

    const uint32_t ahb = sbase + S2_AH, alb = sbase + S2_AL;
    const uint32_t bhb = sbase + S2_BH, blb = sbase + S2_BL;
    const uint32_t a_off = a_lane_off<S2AB>(lane);
    const uint32_t b_off = b_lane_off<S2AB>(lane);
    const uint32_t awm = (uint32_t)(warp_m * 32 * S2AB);
    const uint32_t bwn = (uint32_t)(warp_n * 32 * S2AB);

    // B fill mapping: 64 rows x 64 k = 1024 float4 -> 4 per thread
    int brow[4], bc4[4];
#pragma unroll
    for (int i = 0; i < 4; ++i) { int id = tid + i * 256; brow[i] = id >> 4; bc4[i] = (id & 15) << 2; }

    // prefetch B for o-tile 0
    float4 vb[4];
#pragma unroll
    for (int i = 0; i < 4; ++i)
        vb[i] = *(const float4*)(ug + (size_t)brow[i] * RANK_ + bc4[i]);

    // ---- A prologue: sum 4 partials, split, STS (once) ----
    // 128 rows x 64 k = 2048 float4 -> 8 per thread
#pragma unroll
    for (int i = 0; i < 8; ++i) {
        int id = tid + i * 256;
        int row = id >> 4, c4 = (id & 15) << 2;
        size_t go = (size_t)row * RANK_ + c4;
        float4 p0 = *(const float4*)(h0 + go);
        float4 p1 = *(const float4*)(h1 + go);
        float4 p2 = *(const float4*)(h2 + go);
        float4 p3 = *(const float4*)(h3 + go);
        float4 v;
        v.x = (p0.x + p1.x) + (p2.x + p3.x);
        v.y = (p0.y + p1.y) + (p2.y + p3.y);
        v.z = (p0.z + p1.z) + (p2.z + p3.z);
        v.w = (p0.w + p1.w) + (p2.w + p3.w);
        uint32_t h01, h23, l01, l23;
        split4(v, h01, h23, l01, l23);
        uint32_t off = (uint32_t)(row * S2AB + c4 * 2);
        *(uint2*)(smem2 + S2_AH + off) = make_uint2(h01, h23);
        *(uint2*)(smem2 + S2_AL + off) = make_uint2(l01, l23);
    }

    // ---- loop over 4 o-tiles ----
    for (int t = 0; t < NOTILE; ++t) {
        __syncthreads();   // B buffer free (prev compute done); also A ready on t=0
#pragma unroll
        for (int i = 0; i < 4; ++i) {
            uint32_t h01, h23, l01, l23;
            split4(vb[i], h01, h23, l01, l23);
            uint32_t off = (uint32_t)(brow[i] * S2AB + bc4[i] * 2);
            *(uint2*)(smem2 + S2_BH + off) = make_uint2(h01, h23);
            *(uint2*)(smem2 + S2_BL + off) = make_uint2(l01, l23);
        }
        __syncthreads();

        if (t + 1 < NOTILE) {
            const float* ugn = ug + (size_t)(t + 1) * 64 * RANK_;
#pragma unroll
            for (int i = 0; i < 4; ++i)
                vb[i] = *(const float4*)(ugn + (size_t)brow[i] * RANK_ + bc4[i]);
        }

        float acc[2][4][4];
#pragma unroll
        for (int q = 0; q < 2; ++q)
#pragma unroll
            for (int n = 0; n < 4; ++n)
#pragma unroll
                for (int j = 0; j < 4; ++j) acc[q][n][j] = 0.f;

#pragma unroll
        for (int k = 0; k < 4; ++k) {   // 4 k16 steps, +32B per step
            k16_compute<S2AB>(ahb + awm + k * 32, alb + awm + k * 32,
                              bhb + bwn + k * 32, blb + bwn + k * 32,
                              a_off, b_off, acc);
        }

        float* og = out + ((size_t)b * S_ + s0) * DOUT_ + og0 + t * 64;
#pragma unroll
        for (int q = 0; q < 2; ++q)
#pragma unroll
            for (int n8 = 0; n8 < 4; ++n8) {
                int m = warp_m * 32 + q * 16 + (lane >> 2);
                int n = warp_n * 32 + n8 * 8 + (lane & 3) * 2;
                *(float2*)(og + (size_t)m * DOUT_ + n)       = make_float2(acc[q][n8][0], acc[q][n8][1]);
                *(float2*)(og + (size_t)(m + 8) * DOUT_ + n) = make_float2(acc[q][n8][2], acc[q][n8][3]);
            }
    }
}

extern "C" void kernel_launch(void* const* d_in, const int* in_sizes, int n_in,
                              void* d_out, int out_size) {
    const float* x     = (const float*)d_in[0];   // [8,1024,1280] f32
    const float* embed = (const float*)d_in[1];   // [8,163840]    f32
    float* out = (float*)d_out;                   // [8,1024,1280] f32

    cudaFuncSetAttribute(stage2_kernel, cudaFuncAttributeMaxDynamicSharedMemorySize, S2_SMEM);

    stage1_kernel<<<dim3(S_ / 128, KSPLIT, B_), 256>>>(x, embed);
    stage2_kernel<<<dim3(DOUT_ / (NOTILE * 64), S_ / 128, B_), 256, S2_SMEM>>>(embed, out);
}